// round 17
// baseline (speedup 1.0000x reference)
#include <cuda_runtime.h>
#include <math.h>
#include <stdint.h>

#define NBATCH  128
#define NH_     256
#define NHC_    128
#define NU_     64
#define NY_     64
#define NCHUNK  32
#define TCH     32

// ---- strides (fp32 words) ---------------------------------------------------
#define SBP  68      // B' half tile [128][68]
#define SUS  68      // U tile [32][68]
#define SXS  132     // X/W tiles [.][132]

// ---- smem offsets (bytes) ---------------------------------------------------
#define OFF_BP   0                    // 128*68*4 = 34816
#define OFF_U    34816                // 32*68*4 = 8704
#define OFF_BUX0 43520                // 32*132*4 = 16896
#define OFF_BUX1 60416                // 32*132*4 = 16896 (ends 77312)
#define OFF_WST  43520                // W staging [64][132] fp32 (ALIAS over BUX; read once at hoist)
#define OFF_X0   77312                // 128 fp32
#define SMEM_TOTAL 77824

// ---- helpers ----------------------------------------------------------------
__device__ __forceinline__ uint32_t sptr(const void* p) {
    return (uint32_t)__cvta_generic_to_shared(p);
}
__device__ __forceinline__ float tf32r(float a) {
    uint32_t u;
    asm("cvt.rna.tf32.f32 %0, %1;" : "=r"(u) : "f"(a));
    return __uint_as_float(u);
}
__device__ __forceinline__ void mma_tf32(float* c, const uint32_t* a, const uint32_t* b) {
    asm volatile(
        "mma.sync.aligned.m16n8k8.row.col.f32.tf32.tf32.f32 "
        "{%0,%1,%2,%3}, {%4,%5,%6,%7}, {%8,%9}, {%0,%1,%2,%3};"
        : "+f"(c[0]), "+f"(c[1]), "+f"(c[2]), "+f"(c[3])
        : "r"(a[0]), "r"(a[1]), "r"(a[2]), "r"(a[3]), "r"(b[0]), "r"(b[1]));
}
#define LDSM_X4(r0, r1, r2, r3, addr)                                        \
    asm volatile("ldmatrix.sync.aligned.m8n8.x4.shared.b16 {%0,%1,%2,%3}, [%4];" \
                 : "=r"(r0), "=r"(r1), "=r"(r2), "=r"(r3) : "r"(addr))
#define BAR_SYNC(id)   asm volatile("bar.sync %0, 256;"   :: "r"(id) : "memory")
#define BAR_ARRIVE(id) asm volatile("bar.arrive %0, 256;" :: "r"(id) : "memory")
#define BAR_P()        asm volatile("bar.sync 1, 128;" ::: "memory")
// bar 1: producer internal; 2+buf: buffer full; 4+buf: buffer empty

// ---- Y init: Y[m][n] = bias[n] ----------------------------------------------
__global__ void k_init(const float* __restrict__ bias, float4* __restrict__ Y4) {
    int idx = blockIdx.x * 256 + threadIdx.x;       // 0 .. 2097151
    const float4* b4 = reinterpret_cast<const float4*>(bias);
    Y4[idx] = b4[idx & 15];
}

// ---- fused warp-specialized kernel, half-channel split ----------------------
__global__ void __launch_bounds__(256, 2)
k_fused(const float* __restrict__ y0,   const float* __restrict__ U,
        const float* __restrict__ lre,  const float* __restrict__ lim,
        const float* __restrict__ B,    const float* __restrict__ W_y2x,
        const float* __restrict__ b_y2x,const float* __restrict__ W_x2y,
        const float* __restrict__ b_x2y,float* __restrict__ Y) {
    extern __shared__ char sm[];
    float* sBp  = (float*)(sm + OFF_BP);
    float* sU   = (float*)(sm + OFF_U);
    float* sWst = (float*)(sm + OFF_WST);
    float* sX0  = (float*)(sm + OFF_X0);

    int tid   = threadIdx.x;
    int b     = blockIdx.x;
    int half  = blockIdx.y;            // channel half: [half*64, half*64+64)
    int hbase = half * 64;
    int lane  = tid & 31;
    int g = lane >> 2, tg = lane & 3;
    int j8 = lane >> 3, r8 = lane & 7;
    uint32_t smb = sptr(sm);

    // ======== init: B' half = tf32(B*nf), local dims interleaved re/im =======
    {
        int d   = tid >> 1;            // local dim 0..127
        int sub = tid & 1;             // half of the 64 K-cols
        int j    = d >> 1;             // local channel
        int comp = d & 1;
        int gh   = comp * NHC_ + hbase + j;
        float a  = fabsf(__ldg(lre + hbase + j));
        float nf = sqrtf(1.0f - expf(-2.0f * a));
        const float4* src = reinterpret_cast<const float4*>(B + gh * NU_) + sub * 8;
        #pragma unroll
        for (int q = 0; q < 8; q++) {
            float4 v = __ldg(src + q);
            v.x = tf32r(v.x * nf); v.y = tf32r(v.y * nf);
            v.z = tf32r(v.z * nf); v.w = tf32r(v.w * nf);
            *(float4*)&sBp[d * SBP + sub * 32 + q * 4] = v;
        }
    }
    // ======== init: W staging [64 n][128 local k], tf32 (init-only scatter) ==
    {
        int n    = tid >> 2;
        int part = tid & 3;
        #pragma unroll
        for (int dd = 0; dd < 32; dd++) {
            int d    = part * 32 + dd;
            int j    = d >> 1;
            int comp = d & 1;
            int gcol = comp * NHC_ + hbase + j;
            sWst[n * SXS + d] = tf32r(__ldg(W_x2y + n * NH_ + gcol));
        }
    }
    // ======== init: x0 local half ========
    if (tid < 128) {
        int d    = tid;
        int j    = d >> 1;
        int comp = d & 1;
        int gh   = comp * NHC_ + hbase + j;
        float acc = __ldg(b_y2x + gh);
        const float* w = W_y2x + gh * NY_;
        const float* y = y0 + b * NY_;
        #pragma unroll
        for (int k = 0; k < NY_; k++) acc = fmaf(__ldg(y + k), __ldg(w + k), acc);
        sX0[d] = acc;
    }

    // ======== producer U(0) prefetch ========
    int urow = tid >> 2, uq = tid & 3;
    float4 ureg[4];
    if (tid < 128) {
        const float4* src = reinterpret_cast<const float4*>(
            U + ((size_t)urow * NBATCH + b) * NU_);
        #pragma unroll
        for (int j = 0; j < 4; j++) ureg[j] = __ldg(src + uq * 4 + j);
    }
    __syncthreads();

    if (tid < 128) {
        // =================== PRODUCER (warps 0-3) ===================
        float slr = 0.f, sli = 0.f, czr = 0.f, czi = 0.f;
        if (tid < 64) {
            int gc   = hbase + tid;
            float a  = fabsf(__ldg(lre + gc));
            float rr_ = expf(-a);
            float th = 1.5707963267948966f * __ldg(lim + gc);
            slr = rr_ * cosf(th);
            sli = rr_ * sinf(th);
            czr = sX0[2 * tid];
            czi = sX0[2 * tid + 1];
        }
        int warp = tid >> 5;
        int wn0  = warp * 32;

        uint32_t aU = sptr(sU) + (((j8 & 1) * 8 + r8) * SUS) * 4 + (j8 >> 1) * 16;
        uint32_t aB = sptr(sBp) + ((wn0 + (j8 >> 1) * 8 + r8) * SBP) * 4 + (j8 & 1) * 16;

        for (int c = 0; c < NCHUNK; c++) {
            int buf = c & 1;
            float* bx = (float*)(sm + (buf ? OFF_BUX1 : OFF_BUX0));
            BAR_SYNC(4 + buf);               // wait buffer empty

            // STS U(c), tf32-rounded
            #pragma unroll
            for (int j = 0; j < 4; j++) {
                float4 v = ureg[j];
                v.x = tf32r(v.x); v.y = tf32r(v.y);
                v.z = tf32r(v.z); v.w = tf32r(v.w);
                *(float4*)&sU[urow * SUS + uq * 16 + j * 4] = v;
            }
            BAR_P();
            if (c < NCHUNK - 1) {
                const float4* src = reinterpret_cast<const float4*>(
                    U + ((size_t)((c + 1) * TCH + urow) * NBATCH + b) * NU_);
                #pragma unroll
                for (int j = 0; j < 4; j++) ureg[j] = __ldg(src + uq * 4 + j);
            }

            // ---- GEMM1: M=32, warp n-slice 32 (local dims), K=64 ----
            float C[2][4][4];
            #pragma unroll
            for (int mt = 0; mt < 2; mt++)
                #pragma unroll
                for (int nt = 0; nt < 4; nt++)
                    #pragma unroll
                    for (int i = 0; i < 4; i++) C[mt][nt][i] = 0.0f;

            #pragma unroll
            for (int ks = 0; ks < 8; ks++) {
                int k0 = ks * 8;
                uint32_t A[2][4];
                #pragma unroll
                for (int mt = 0; mt < 2; mt++)
                    LDSM_X4(A[mt][0], A[mt][1], A[mt][2], A[mt][3],
                            aU + (mt * 16 * SUS + k0) * 4);
                uint32_t Bf[4][2];
                #pragma unroll
                for (int ntp = 0; ntp < 2; ntp++)
                    LDSM_X4(Bf[ntp*2][0], Bf[ntp*2][1], Bf[ntp*2+1][0], Bf[ntp*2+1][1],
                            aB + (ntp * 16 * SBP + k0) * 4);
                #pragma unroll
                for (int mt = 0; mt < 2; mt++)
                    #pragma unroll
                    for (int nt = 0; nt < 4; nt++)
                        mma_tf32(C[mt][nt], A[mt], Bf[nt]);
            }
            // epilogue -> bx fp32
            #pragma unroll
            for (int mt = 0; mt < 2; mt++)
                #pragma unroll
                for (int nt = 0; nt < 4; nt++) {
                    int r = mt * 16 + g;
                    int n = wn0 + nt * 8 + 2 * tg;
                    *(float2*)&bx[r * SXS + n]       = make_float2(C[mt][nt][0], C[mt][nt][1]);
                    *(float2*)&bx[(r + 8) * SXS + n] = make_float2(C[mt][nt][2], C[mt][nt][3]);
                }
            BAR_P();

            // ---- scan (threads 0-63, re/im adjacent); tf32-rounded stores ----
            if (tid < 64) {
                float zr = czr, zi = czi;
                #pragma unroll 4
                for (int t = 0; t < TCH; t++) {
                    float2 u = *(const float2*)&bx[t * SXS + 2 * tid];
                    float nr = fmaf(slr, zr, fmaf(-sli, zi, u.x));
                    float ni = fmaf(sli, zr, fmaf( slr, zi, u.y));
                    zr = nr; zi = ni;
                    *(float2*)&bx[t * SXS + 2 * tid] =
                        make_float2(tf32r(zr), tf32r(zi));
                }
                czr = zr; czi = zi;
            }
            BAR_ARRIVE(2 + buf);             // buffer full
        }
    } else {
        // =================== CONSUMER (warps 4-7) ===================
        int qw  = (tid >> 5) - 4;
        int wn0 = qw * 16;
        // hoist W slice fragments: 16 ksteps x 2 n8 x 2 regs (reads the ALIASED
        // staging region; must finish BEFORE arriving on the empty barriers)
        uint32_t aW = sptr(sWst) + ((wn0 + (j8 >> 1) * 8 + r8) * SXS) * 4 + (j8 & 1) * 16;
        uint32_t Wfr[16][2][2];
        #pragma unroll
        for (int ks = 0; ks < 16; ks++)
            LDSM_X4(Wfr[ks][0][0], Wfr[ks][0][1], Wfr[ks][1][0], Wfr[ks][1][1],
                    aW + ks * 32);
        BAR_ARRIVE(4);
        BAR_ARRIVE(5);
        uint32_t aX0b = (((j8 & 1) * 8 + r8) * SXS) * 4 + (j8 >> 1) * 16;

        for (int c = 0; c < NCHUNK; c++) {
            int buf = c & 1;
            uint32_t aX = smb + (buf ? OFF_BUX1 : OFF_BUX0) + aX0b;
            BAR_SYNC(2 + buf);               // wait full

            float C[2][2][4];
            #pragma unroll
            for (int mt = 0; mt < 2; mt++)
                #pragma unroll
                for (int nt = 0; nt < 2; nt++)
                    #pragma unroll
                    for (int i = 0; i < 4; i++) C[mt][nt][i] = 0.0f;

            #pragma unroll
            for (int ks = 0; ks < 16; ks++) {
                int k0 = ks * 8;
                uint32_t A[2][4];
                #pragma unroll
                for (int mt = 0; mt < 2; mt++)
                    LDSM_X4(A[mt][0], A[mt][1], A[mt][2], A[mt][3],
                            aX + (mt * 16 * SXS + k0) * 4);
                #pragma unroll
                for (int mt = 0; mt < 2; mt++)
                    #pragma unroll
                    for (int nt = 0; nt < 2; nt++)
                        mma_tf32(C[mt][nt], A[mt], Wfr[ks][nt]);
            }
            BAR_ARRIVE(4 + buf);             // buffer empty

            // partial Y via atomic add (Y pre-initialized with bias)
            #pragma unroll
            for (int mt = 0; mt < 2; mt++)
                #pragma unroll
                for (int nt = 0; nt < 2; nt++) {
                    int n  = wn0 + nt * 8 + 2 * tg;
                    int t0 = c * TCH + mt * 16 + g;
                    float* p0 = Y + ((size_t)t0 * NBATCH + b) * NY_ + n;
                    float* p1 = Y + ((size_t)(t0 + 8) * NBATCH + b) * NY_ + n;
                    atomicAdd(p0,     C[mt][nt][0]);
                    atomicAdd(p0 + 1, C[mt][nt][1]);
                    atomicAdd(p1,     C[mt][nt][2]);
                    atomicAdd(p1 + 1, C[mt][nt][3]);
                }
        }
    }
}

// ---- launch -----------------------------------------------------------------
extern "C" void kernel_launch(void* const* d_in, const int* in_sizes, int n_in,
                              void* d_out, int out_size) {
    const float* y0     = (const float*)d_in[0];
    const float* U      = (const float*)d_in[1];
    const float* lre    = (const float*)d_in[2];
    const float* lim    = (const float*)d_in[3];
    const float* B      = (const float*)d_in[4];
    const float* W_y2x  = (const float*)d_in[5];
    const float* b_y2x  = (const float*)d_in[6];
    const float* W_x2y  = (const float*)d_in[7];
    const float* b_x2y  = (const float*)d_in[8];
    float*       Y      = (float*)d_out;

    cudaFuncSetAttribute(k_fused, cudaFuncAttributeMaxDynamicSharedMemorySize,
                         SMEM_TOTAL);
    // Y = bias (8.4M floats = 2.1M float4)
    k_init<<<8192, 256>>>(b_x2y, (float4*)Y);
    dim3 grid(NBATCH, 2);
    k_fused<<<grid, 256, SMEM_TOTAL>>>(y0, U, lre, lim, B, W_y2x, b_y2x,
                                       W_x2y, b_x2y, Y);
}